// round 1
// baseline (speedup 1.0000x reference)
#include <cuda_runtime.h>
#include <math.h>

// Problem constants
#define B_  2
#define C1_ 256
#define C2_ 256
#define K2_ 9
#define H_  64
#define W_  64
#define HW_ 4096

// Scratch (allocation-free: __device__ globals)
__device__ float g_dy[B_ * K2_ * HW_];
__device__ float g_dx[B_ * K2_ * HW_];
__device__ float g_mask[B_ * K2_ * HW_];
__device__ float g_wT[K2_ * C1_ * C2_];     // [k][c][o]
__device__ float g_woffT[C1_ * 9 * 27];     // [(c*9+kk)][oc]

// ---------------------------------------------------------------------------
// Kernel 0: transpose weights for coalesced staging later
// ---------------------------------------------------------------------------
__global__ void transpose_weights(const float* __restrict__ w_dcn,
                                  const float* __restrict__ w_off) {
    int idx = blockIdx.x * 256 + threadIdx.x;
    if (idx < K2_ * C1_ * C2_) {
        int k = idx / (C1_ * C2_);
        int r = idx % (C1_ * C2_);
        int c = r / C2_;
        int o = r % C2_;
        g_wT[idx] = w_dcn[o * (C1_ * K2_) + c * K2_ + k];
    }
    if (idx < C1_ * 9 * 27) {
        int ck = idx / 27;      // c*9+kk
        int oc = idx % 27;
        g_woffT[idx] = w_off[oc * (C1_ * 9) + ck];
    }
}

// ---------------------------------------------------------------------------
// Kernel 1: 3x3 offset conv -> dy, dx, sigmoid(mask)
// One CTA per (b, h) row; 256 threads = 4 oc-groups x 64 pixels.
// ---------------------------------------------------------------------------
__global__ __launch_bounds__(256) void conv_off(const float* __restrict__ x,
                                                const float* __restrict__ b_off) {
    int b = blockIdx.x >> 6;
    int h = blockIdx.x & 63;
    int tid = threadIdx.x;
    int w = tid & 63;
    int g = tid >> 6;          // 0..3
    int oc0 = g * 7;           // groups: 7,7,7,6 channels

    __shared__ float xs[16][3][64];   // [c][ky][w]
    __shared__ float ws[16][9][28];   // [c][kk][oc], padded to 28

    float acc[7];
#pragma unroll
    for (int j = 0; j < 7; j++) acc[j] = 0.f;

    for (int cc = 0; cc < C1_; cc += 16) {
        // stage x rows h-1..h+1 for 16 channels
        for (int i = tid; i < 16 * 3 * 64; i += 256) {
            int c = i / 192, r = i % 192;
            int ky = r / 64, ww = r % 64;
            int y = h - 1 + ky;
            xs[c][ky][ww] = (y >= 0 && y < H_)
                ? x[((b * C1_ + cc + c) * H_ + y) * W_ + ww] : 0.f;
        }
        // stage weights
        for (int i = tid; i < 16 * 9 * 28; i += 256) {
            int c = i / 252, r = i % 252;
            int kk = r / 28, oc = r % 28;
            ws[c][kk][oc] = (oc < 27) ? g_woffT[((cc + c) * 9 + kk) * 27 + oc] : 0.f;
        }
        __syncthreads();

        for (int c = 0; c < 16; c++) {
#pragma unroll
            for (int kk = 0; kk < 9; kk++) {
                int ky = kk / 3, kx = kk % 3;
                int ww = w + kx - 1;
                float xv = (ww >= 0 && ww < W_) ? xs[c][ky][ww] : 0.f;
#pragma unroll
                for (int j = 0; j < 7; j++)
                    acc[j] += xv * ws[c][kk][oc0 + j];
            }
        }
        __syncthreads();
    }

    // write results
#pragma unroll
    for (int j = 0; j < 7; j++) {
        int oc = oc0 + j;
        if (oc >= 27) break;
        float v = acc[j] + b_off[oc];
        if (oc < 18) {
            int k = oc >> 1;
            int oo = (b * K2_ + k) * HW_ + (h << 6) + w;
            if (oc & 1) g_dx[oo] = v; else g_dy[oo] = v;
        } else {
            int k = oc - 18;
            int oo = (b * K2_ + k) * HW_ + (h << 6) + w;
            g_mask[oo] = 1.f / (1.f + __expf(-v));
        }
    }
}

// ---------------------------------------------------------------------------
// Kernel 2: main DCN GEMM + BN + SiLU.
// One CTA per (b, h): 64 pixels x 256 output channels.
// Per tap: build sampled tile s[256c][64p] in smem, then register-tiled GEMM.
// Thread (ty, tx) = (tid/16, tid%16) owns o in [ty*16, ty*16+16), p in [tx*4, tx*4+4).
// ---------------------------------------------------------------------------
#define SMEM_S  (C1_ * 64)        // 16384 floats
#define SMEM_W  (32 * C2_)        // 8192 floats
#define SMEM_FLOATS (SMEM_S + SMEM_W + 256 + 256)

extern __shared__ float sm[];

__global__ __launch_bounds__(256) void dcn_main(const float* __restrict__ x,
                                                const float* __restrict__ gamma,
                                                const float* __restrict__ beta,
                                                const float* __restrict__ rmean,
                                                const float* __restrict__ rvar,
                                                float* __restrict__ out) {
    int b = blockIdx.x >> 6;
    int h = blockIdx.x & 63;
    int tid = threadIdx.x;
    int tx = tid & 15;    // p dim
    int ty = tid >> 4;    // o dim

    float* s_s  = sm;                       // [c*64 + p]
    float* s_w  = sm + SMEM_S;              // [c_local*256 + o]
    float* swt  = sm + SMEM_S + SMEM_W;     // [corner*64 + p]
    int*   sidx = (int*)(swt + 256);        // [corner*64 + p]

    float acc[16][4];
#pragma unroll
    for (int i = 0; i < 16; i++)
#pragma unroll
        for (int j = 0; j < 4; j++) acc[i][j] = 0.f;

    const float* xb = x + b * C1_ * HW_;

    for (int k = 0; k < 9; k++) {
        // --- per-pixel bilinear metadata (64 threads), mask folded into weights
        if (tid < 64) {
            int w = tid;
            int oo = (b * K2_ + k) * HW_ + (h << 6) + w;
            float py = (float)(h - 1 + k / 3) + g_dy[oo];
            float px = (float)(w - 1 + k % 3) + g_dx[oo];
            float m = g_mask[oo];
            float y0f = floorf(py), x0f = floorf(px);
            float ly = py - y0f, lx = px - x0f;
            int y0 = (int)y0f, x0 = (int)x0f;
            int y1 = y0 + 1, x1 = x0 + 1;
            float vy0 = (y0 >= 0 && y0 < H_) ? 1.f : 0.f;
            float vy1 = (y1 >= 0 && y1 < H_) ? 1.f : 0.f;
            float vx0 = (x0 >= 0 && x0 < W_) ? 1.f : 0.f;
            float vx1 = (x1 >= 0 && x1 < W_) ? 1.f : 0.f;
            int cy0 = min(max(y0, 0), H_ - 1), cy1 = min(max(y1, 0), H_ - 1);
            int cx0 = min(max(x0, 0), W_ - 1), cx1 = min(max(x1, 0), W_ - 1);
            swt[0 * 64 + w] = (1.f - ly) * (1.f - lx) * m * vy0 * vx0;
            swt[1 * 64 + w] = (1.f - ly) * lx * m * vy0 * vx1;
            swt[2 * 64 + w] = ly * (1.f - lx) * m * vy1 * vx0;
            swt[3 * 64 + w] = ly * lx * m * vy1 * vx1;
            sidx[0 * 64 + w] = cy0 * W_ + cx0;
            sidx[1 * 64 + w] = cy0 * W_ + cx1;
            sidx[2 * 64 + w] = cy1 * W_ + cx0;
            sidx[3 * 64 + w] = cy1 * W_ + cx1;
        }
        __syncthreads();

        // --- gather sampled tile s[c][p] (p fixed per thread -> metadata hoisted)
        {
            int p = tid & 63;
            int i0 = sidx[p],       i1 = sidx[64 + p];
            int i2 = sidx[128 + p], i3 = sidx[192 + p];
            float w0 = swt[p],       w1 = swt[64 + p];
            float w2 = swt[128 + p], w3 = swt[192 + p];
            for (int i = tid; i < C1_ * 64; i += 256) {
                int c = i >> 6;
                const float* xc = xb + (c << 12);
                s_s[i] = xc[i0] * w0 + xc[i1] * w1 + xc[i2] * w2 + xc[i3] * w3;
            }
        }

        // --- GEMM: acc[o][p] += sum_c wT[k][c][o] * s[c][p], chunks of 32 c
        const float* wk = g_wT + k * (C1_ * C2_);
        for (int c0 = 0; c0 < C1_; c0 += 32) {
            for (int i = tid; i < SMEM_W; i += 256)
                s_w[i] = wk[c0 * C2_ + i];
            __syncthreads();
#pragma unroll
            for (int c = 0; c < 32; c++) {
                const float4 sv = *(const float4*)(s_s + (c0 + c) * 64 + (tx << 2));
                const float* wr = s_w + c * C2_ + (ty << 4);
#pragma unroll
                for (int j = 0; j < 4; j++) {
                    float4 wv = *(const float4*)(wr + (j << 2));
                    acc[j * 4 + 0][0] += wv.x * sv.x;
                    acc[j * 4 + 0][1] += wv.x * sv.y;
                    acc[j * 4 + 0][2] += wv.x * sv.z;
                    acc[j * 4 + 0][3] += wv.x * sv.w;
                    acc[j * 4 + 1][0] += wv.y * sv.x;
                    acc[j * 4 + 1][1] += wv.y * sv.y;
                    acc[j * 4 + 1][2] += wv.y * sv.z;
                    acc[j * 4 + 1][3] += wv.y * sv.w;
                    acc[j * 4 + 2][0] += wv.z * sv.x;
                    acc[j * 4 + 2][1] += wv.z * sv.y;
                    acc[j * 4 + 2][2] += wv.z * sv.z;
                    acc[j * 4 + 2][3] += wv.z * sv.w;
                    acc[j * 4 + 3][0] += wv.w * sv.x;
                    acc[j * 4 + 3][1] += wv.w * sv.y;
                    acc[j * 4 + 3][2] += wv.w * sv.z;
                    acc[j * 4 + 3][3] += wv.w * sv.w;
                }
            }
            __syncthreads();
        }
    }

    // --- epilogue: BN (inference) + SiLU, coalesced float4 stores
#pragma unroll
    for (int i = 0; i < 16; i++) {
        int o = (ty << 4) + i;
        float inv = gamma[o] * rsqrtf(rvar[o] + 1e-5f);
        float bb = beta[o] - rmean[o] * inv;
        float4 r;
        float y0v = acc[i][0] * inv + bb;
        float y1v = acc[i][1] * inv + bb;
        float y2v = acc[i][2] * inv + bb;
        float y3v = acc[i][3] * inv + bb;
        r.x = y0v / (1.f + __expf(-y0v));
        r.y = y1v / (1.f + __expf(-y1v));
        r.z = y2v / (1.f + __expf(-y2v));
        r.w = y3v / (1.f + __expf(-y3v));
        *(float4*)(out + ((b * C2_ + o) * H_ + h) * W_ + (tx << 2)) = r;
    }
}

// ---------------------------------------------------------------------------
extern "C" void kernel_launch(void* const* d_in, const int* in_sizes, int n_in,
                              void* d_out, int out_size) {
    const float* x      = (const float*)d_in[0];
    const float* w_off  = (const float*)d_in[1];
    const float* b_off  = (const float*)d_in[2];
    const float* w_dcn  = (const float*)d_in[3];
    const float* gamma  = (const float*)d_in[4];
    const float* beta   = (const float*)d_in[5];
    const float* rmean  = (const float*)d_in[6];
    const float* rvar   = (const float*)d_in[7];
    float* out = (float*)d_out;

    const int smem_bytes = SMEM_FLOATS * 4;  // 100352 B
    cudaFuncSetAttribute(dcn_main, cudaFuncAttributeMaxDynamicSharedMemorySize,
                         smem_bytes);

    transpose_weights<<<(K2_ * C1_ * C2_ + 255) / 256, 256>>>(w_dcn, w_off);
    conv_off<<<B_ * H_, 256>>>(x, b_off);
    dcn_main<<<B_ * H_, 256, smem_bytes>>>(x, gamma, beta, rmean, rvar, out);
}

// round 3
// speedup vs baseline: 2.0280x; 2.0280x over previous
#include <cuda_runtime.h>
#include <cuda_bf16.h>
#include <cstdint>
#include <math.h>

// Problem constants
#define B_  2
#define C1_ 256
#define C2_ 256
#define K2_ 9
#define H_  64
#define W_  64
#define HW_ 4096

// ---------------------------------------------------------------------------
// Scratch (allocation-free: __device__ globals)
// ---------------------------------------------------------------------------
__device__ float g_dy[B_ * K2_ * HW_];
__device__ float g_dx[B_ * K2_ * HW_];
__device__ float g_mask[B_ * K2_ * HW_];
__device__ float g_woffT[C1_ * 9 * 27];     // [(c*9+kk)][oc]
// Packed weights: [tap(9)][chunk(4)][hl(2)][o(256)][72 bf16] (c-chunk of 64 + pad)
// chunk stride = 2*256*72*2 = 73728 B ; total 9*4*73728 = 2654208 B
__device__ __align__(128) __nv_bfloat16 g_wA[9 * 4 * 2 * 256 * 72];

// ---------------------------------------------------------------------------
// PTX helpers (all legal on plain sm_103 target: sm_80-era instructions)
// ---------------------------------------------------------------------------
__device__ __forceinline__ uint32_t smem_u32(const void* p) {
    uint32_t a;
    asm("{ .reg .u64 t; cvta.to.shared.u64 t, %1; cvt.u32.u64 %0, t; }"
        : "=r"(a) : "l"(p));
    return a;
}

__device__ __forceinline__ void cp_async16(uint32_t saddr, const void* gaddr) {
    asm volatile("cp.async.cg.shared.global [%0], [%1], 16;"
                 :: "r"(saddr), "l"(gaddr) : "memory");
}
__device__ __forceinline__ void cp_commit() {
    asm volatile("cp.async.commit_group;" ::: "memory");
}
__device__ __forceinline__ void cp_wait1() {
    asm volatile("cp.async.wait_group 1;" ::: "memory");
}
__device__ __forceinline__ void cp_wait0() {
    asm volatile("cp.async.wait_group 0;" ::: "memory");
}

__device__ __forceinline__ void ldmatrix_x4(uint32_t& r0, uint32_t& r1,
                                            uint32_t& r2, uint32_t& r3,
                                            uint32_t addr) {
    asm volatile("ldmatrix.sync.aligned.m8n8.x4.shared.b16 {%0,%1,%2,%3}, [%4];"
                 : "=r"(r0), "=r"(r1), "=r"(r2), "=r"(r3) : "r"(addr));
}

__device__ __forceinline__ void mma_bf16(float& d0, float& d1, float& d2, float& d3,
                                         uint32_t a0, uint32_t a1, uint32_t a2, uint32_t a3,
                                         uint32_t b0, uint32_t b1) {
    asm volatile(
        "mma.sync.aligned.m16n8k16.row.col.f32.bf16.bf16.f32 "
        "{%0,%1,%2,%3}, {%4,%5,%6,%7}, {%8,%9}, {%0,%1,%2,%3};"
        : "+f"(d0), "+f"(d1), "+f"(d2), "+f"(d3)
        : "r"(a0), "r"(a1), "r"(a2), "r"(a3), "r"(b0), "r"(b1));
}

// ---------------------------------------------------------------------------
// Kernel 0: pack w_dcn -> bf16 hi/lo chunked blobs; transpose w_off
// ---------------------------------------------------------------------------
__global__ void pack_weights(const float* __restrict__ w_dcn,
                             const float* __restrict__ w_off) {
    int idx = blockIdx.x * 256 + threadIdx.x;
    if (idx < 9 * 256 * 256) {
        int t = idx >> 16;
        int r = idx & 65535;
        int o = r >> 8;
        int c = r & 255;
        float w = w_dcn[o * (C1_ * K2_) + c * K2_ + t];
        __nv_bfloat16 hi = __float2bfloat16(w);
        __nv_bfloat16 lo = __float2bfloat16(w - __bfloat162float(hi));
        int chunk = c >> 6, cl = c & 63;
        size_t base = ((size_t)(t * 4 + chunk) * 2) * (256 * 72) + (size_t)o * 72 + cl;
        g_wA[base]            = hi;           // hl=0
        g_wA[base + 256 * 72] = lo;           // hl=1
    }
    if (idx < C1_ * 9 * 27) {
        int ck = idx / 27, oc = idx % 27;
        g_woffT[idx] = w_off[oc * (C1_ * 9) + ck];
    }
}

// ---------------------------------------------------------------------------
// Kernel 1: 3x3 offset conv -> dy, dx, sigmoid(mask)   (unchanged, passing)
// ---------------------------------------------------------------------------
__global__ __launch_bounds__(256) void conv_off(const float* __restrict__ x,
                                                const float* __restrict__ b_off) {
    int b = blockIdx.x >> 6;
    int h = blockIdx.x & 63;
    int tid = threadIdx.x;
    int w = tid & 63;
    int g = tid >> 6;
    int oc0 = g * 7;

    __shared__ float xs[16][3][64];
    __shared__ float ws[16][9][28];

    float acc[7];
#pragma unroll
    for (int j = 0; j < 7; j++) acc[j] = 0.f;

    for (int cc = 0; cc < C1_; cc += 16) {
        for (int i = tid; i < 16 * 3 * 64; i += 256) {
            int c = i / 192, r = i % 192;
            int ky = r / 64, ww = r % 64;
            int y = h - 1 + ky;
            xs[c][ky][ww] = (y >= 0 && y < H_)
                ? x[((b * C1_ + cc + c) * H_ + y) * W_ + ww] : 0.f;
        }
        for (int i = tid; i < 16 * 9 * 28; i += 256) {
            int c = i / 252, r = i % 252;
            int kk = r / 28, oc = r % 28;
            ws[c][kk][oc] = (oc < 27) ? g_woffT[((cc + c) * 9 + kk) * 27 + oc] : 0.f;
        }
        __syncthreads();

        for (int c = 0; c < 16; c++) {
#pragma unroll
            for (int kk = 0; kk < 9; kk++) {
                int ky = kk / 3, kx = kk % 3;
                int ww = w + kx - 1;
                float xv = (ww >= 0 && ww < W_) ? xs[c][ky][ww] : 0.f;
#pragma unroll
                for (int j = 0; j < 7; j++)
                    acc[j] += xv * ws[c][kk][oc0 + j];
            }
        }
        __syncthreads();
    }

#pragma unroll
    for (int j = 0; j < 7; j++) {
        int oc = oc0 + j;
        if (oc >= 27) break;
        float v = acc[j] + b_off[oc];
        if (oc < 18) {
            int k = oc >> 1;
            int oo = (b * K2_ + k) * HW_ + (h << 6) + w;
            if (oc & 1) g_dx[oo] = v; else g_dy[oo] = v;
        } else {
            int k = oc - 18;
            int oo = (b * K2_ + k) * HW_ + (h << 6) + w;
            g_mask[oo] = 1.f / (1.f + __expf(-v));
        }
    }
}

// ---------------------------------------------------------------------------
// Kernel 2: main DCN via mma.sync bf16 split (hi/lo) + BN + SiLU
// One CTA per (b,h): D[256 o][64 p]. 8 warps, warp w -> o in [32w, 32w+32).
// Smem: W double-buffer [2][hl][256][72] bf16; B [hl][64][264] bf16.
// ---------------------------------------------------------------------------
#define WS_STRIDE   72            // bf16 elems per weight row
#define BS_STRIDE   264           // bf16 elems per B row
#define W_CHUNK_B   73728u        // bytes per chunk (2 hl * 256 * 72 * 2)
#define W_HL_B      36864u
#define WS_OFF      0u
#define BS_OFF      147456u       // 2 * W_CHUNK_B
#define BS_HL_B     33792u        // 64 * 264 * 2
#define META_OFF    215040u       // BS_OFF + 2*BS_HL_B
#define SMEM_BYTES  (META_OFF + 2048u)

__global__ __launch_bounds__(256, 1) void dcn_main(const float* __restrict__ x,
                                                   const float* __restrict__ gamma,
                                                   const float* __restrict__ beta,
                                                   const float* __restrict__ rmean,
                                                   const float* __restrict__ rvar,
                                                   float* __restrict__ out) {
    extern __shared__ __align__(128) unsigned char smem_raw[];
    const uint32_t smem_base = smem_u32(smem_raw);

    int b = blockIdx.x >> 6;
    int h = blockIdx.x & 63;
    int tid = threadIdx.x;
    int wid = tid >> 5;
    int lane = tid & 31;

    float* swt  = (float*)(smem_raw + META_OFF);
    int*   sidx = (int*)(smem_raw + META_OFF + 1024);

    const float* xb = x + b * C1_ * HW_;
    int p  = tid & 63;
    int gg = tid >> 6;

    // per-lane ldmatrix row/col adds
    int a_row = lane & 15;                 // A frag row within 16-tile
    int a_cad = (lane >= 16) ? 8 : 0;      // A frag col add (k)
    int b_row = (lane & 7) + ((lane >= 16) ? 8 : 0);   // B frag row within nt-pair
    int b_cad = ((lane >> 3) & 1) * 8;     // B frag col add (k)

    int o0 = wid * 32;

    float acc[2][8][4];
#pragma unroll
    for (int mt = 0; mt < 2; mt++)
#pragma unroll
        for (int nt = 0; nt < 8; nt++)
#pragma unroll
            for (int j = 0; j < 4; j++) acc[mt][nt][j] = 0.f;

    // prefetch chunk 0 (tap 0) into buf 0
    {
        const unsigned char* src = (const unsigned char*)g_wA;
        for (int j = 0; j < 18; j++) {
            uint32_t off = (uint32_t)(tid + 256 * j) * 16u;
            cp_async16(smem_base + WS_OFF + off, src + off);
        }
        cp_commit();
    }

    for (int t = 0; t < 9; ++t) {
        // --- bilinear metadata (mask folded into corner weights)
        if (tid < 64) {
            int w = tid;
            int oo = (b * K2_ + t) * HW_ + (h << 6) + w;
            float py = (float)(h - 1 + t / 3) + g_dy[oo];
            float px = (float)(w - 1 + t % 3) + g_dx[oo];
            float m = g_mask[oo];
            float y0f = floorf(py), x0f = floorf(px);
            float ly = py - y0f, lx = px - x0f;
            int y0 = (int)y0f, x0 = (int)x0f;
            int y1 = y0 + 1, x1 = x0 + 1;
            float vy0 = (y0 >= 0 && y0 < H_) ? 1.f : 0.f;
            float vy1 = (y1 >= 0 && y1 < H_) ? 1.f : 0.f;
            float vx0 = (x0 >= 0 && x0 < W_) ? 1.f : 0.f;
            float vx1 = (x1 >= 0 && x1 < W_) ? 1.f : 0.f;
            int cy0 = min(max(y0, 0), H_ - 1), cy1 = min(max(y1, 0), H_ - 1);
            int cx0 = min(max(x0, 0), W_ - 1), cx1 = min(max(x1, 0), W_ - 1);
            swt[0 * 64 + w] = (1.f - ly) * (1.f - lx) * m * vy0 * vx0;
            swt[1 * 64 + w] = (1.f - ly) * lx * m * vy0 * vx1;
            swt[2 * 64 + w] = ly * (1.f - lx) * m * vy1 * vx0;
            swt[3 * 64 + w] = ly * lx * m * vy1 * vx1;
            sidx[0 * 64 + w] = cy0 * W_ + cx0;
            sidx[1 * 64 + w] = cy0 * W_ + cx1;
            sidx[2 * 64 + w] = cy1 * W_ + cx0;
            sidx[3 * 64 + w] = cy1 * W_ + cx1;
        }
        __syncthreads();

        // --- gather + hi/lo split into B smem [hl][p][264]
        {
            int i0 = sidx[p],       i1 = sidx[64 + p];
            int i2 = sidx[128 + p], i3 = sidx[192 + p];
            float w0 = swt[p],       w1 = swt[64 + p];
            float w2 = swt[128 + p], w3 = swt[192 + p];
            __nv_bfloat162* Bh = (__nv_bfloat162*)(smem_raw + BS_OFF);
            __nv_bfloat162* Bl = (__nv_bfloat162*)(smem_raw + BS_OFF + BS_HL_B);
            int rowb = p * (BS_STRIDE / 2);   // bf16x2 units per row = 132
#pragma unroll 4
            for (int it = 0; it < 32; ++it) {
                int cp = gg + (it << 2);       // c-pair 0..127
                int c0 = cp << 1;
                const float* xa = xb + ((size_t)c0 << 12);
                const float* xc = xa + HW_;
                float va = xa[i0] * w0 + xa[i1] * w1 + xa[i2] * w2 + xa[i3] * w3;
                float vb = xc[i0] * w0 + xc[i1] * w1 + xc[i2] * w2 + xc[i3] * w3;
                __nv_bfloat162 hp = __floats2bfloat162_rn(va, vb);
                float ra = va - __bfloat162float(hp.x);
                float rb = vb - __bfloat162float(hp.y);
                __nv_bfloat162 lp = __floats2bfloat162_rn(ra, rb);
                Bh[rowb + cp] = hp;
                Bl[rowb + cp] = lp;
            }
        }
        __syncthreads();

        // --- 4 c-chunks of 64, double-buffered weights
        for (int q = 0; q < 4; ++q) {
            int ci = t * 4 + q;
            bool has_next = (ci + 1 < 36);
            if (has_next) {
                const unsigned char* src =
                    (const unsigned char*)g_wA + (size_t)(ci + 1) * W_CHUNK_B;
                uint32_t dst = smem_base + WS_OFF + ((q + 1) & 1) * W_CHUNK_B;
                for (int j = 0; j < 18; j++) {
                    uint32_t off = (uint32_t)(tid + 256 * j) * 16u;
                    cp_async16(dst + off, src + off);
                }
                cp_commit();
                cp_wait1();
            } else {
                cp_wait0();
            }
            __syncthreads();

            uint32_t wbuf = smem_base + WS_OFF + (q & 1) * W_CHUNK_B;
            uint32_t bsh  = smem_base + BS_OFF;

#pragma unroll
            for (int ks = 0; ks < 4; ++ks) {
                int kb_w = ks * 16;              // col within weight chunk
                int kb_b = q * 64 + kb_w;        // col within B tile

                // B fragments: hi and lo, 8 n-tiles via 4 ldmatrix.x4 each
                uint32_t Bhf[16], Blf[16];
#pragma unroll
                for (int pr = 0; pr < 4; ++pr) {
                    uint32_t rowB = (uint32_t)(pr * 16 + b_row);
                    uint32_t colB = (uint32_t)(kb_b + b_cad);
                    uint32_t addr = bsh + (rowB * BS_STRIDE + colB) * 2;
                    ldmatrix_x4(Bhf[pr * 4 + 0], Bhf[pr * 4 + 1],
                                Bhf[pr * 4 + 2], Bhf[pr * 4 + 3], addr);
                    ldmatrix_x4(Blf[pr * 4 + 0], Blf[pr * 4 + 1],
                                Blf[pr * 4 + 2], Blf[pr * 4 + 3],
                                addr + BS_HL_B);
                }
#pragma unroll
                for (int mt = 0; mt < 2; ++mt) {
                    uint32_t rowA = (uint32_t)(o0 + mt * 16 + a_row);
                    uint32_t colA = (uint32_t)(kb_w + a_cad);
                    uint32_t aaddr = wbuf + (rowA * WS_STRIDE + colA) * 2;
                    uint32_t Ah0, Ah1, Ah2, Ah3, Al0, Al1, Al2, Al3;
                    ldmatrix_x4(Ah0, Ah1, Ah2, Ah3, aaddr);
                    ldmatrix_x4(Al0, Al1, Al2, Al3, aaddr + W_HL_B);
#pragma unroll
                    for (int nt = 0; nt < 8; ++nt) {
                        uint32_t bh0 = Bhf[nt * 2], bh1 = Bhf[nt * 2 + 1];
                        uint32_t bl0 = Blf[nt * 2], bl1 = Blf[nt * 2 + 1];
                        float* d = acc[mt][nt];
                        mma_bf16(d[0], d[1], d[2], d[3], Ah0, Ah1, Ah2, Ah3, bh0, bh1);
                        mma_bf16(d[0], d[1], d[2], d[3], Ah0, Ah1, Ah2, Ah3, bl0, bl1);
                        mma_bf16(d[0], d[1], d[2], d[3], Al0, Al1, Al2, Al3, bh0, bh1);
                    }
                }
            }
            __syncthreads();
        }
    }

    // --- epilogue: BN + SiLU from register fragments
    {
        int g4 = lane >> 2;          // 0..7 : row within 8
        int t4 = lane & 3;           // 0..3 : col pair
#pragma unroll
        for (int mt = 0; mt < 2; ++mt) {
            int o_lo = o0 + mt * 16 + g4;
            int o_hi = o_lo + 8;
            float invl = gamma[o_lo] * rsqrtf(rvar[o_lo] + 1e-5f);
            float bbl  = beta[o_lo] - rmean[o_lo] * invl;
            float invh = gamma[o_hi] * rsqrtf(rvar[o_hi] + 1e-5f);
            float bbh  = beta[o_hi] - rmean[o_hi] * invh;
            float* opl = out + (((size_t)b * C2_ + o_lo) * H_ + h) * W_;
            float* oph = out + (((size_t)b * C2_ + o_hi) * H_ + h) * W_;
#pragma unroll
            for (int nt = 0; nt < 8; ++nt) {
                int pp = nt * 8 + t4 * 2;
                float y0v = acc[mt][nt][0] * invl + bbl;
                float y1v = acc[mt][nt][1] * invl + bbl;
                float y2v = acc[mt][nt][2] * invh + bbh;
                float y3v = acc[mt][nt][3] * invh + bbh;
                float2 vlo, vhi;
                vlo.x = y0v / (1.f + __expf(-y0v));
                vlo.y = y1v / (1.f + __expf(-y1v));
                vhi.x = y2v / (1.f + __expf(-y2v));
                vhi.y = y3v / (1.f + __expf(-y3v));
                *(float2*)(opl + pp) = vlo;
                *(float2*)(oph + pp) = vhi;
            }
        }
    }
}

// ---------------------------------------------------------------------------
extern "C" void kernel_launch(void* const* d_in, const int* in_sizes, int n_in,
                              void* d_out, int out_size) {
    const float* x      = (const float*)d_in[0];
    const float* w_off  = (const float*)d_in[1];
    const float* b_off  = (const float*)d_in[2];
    const float* w_dcn  = (const float*)d_in[3];
    const float* gamma  = (const float*)d_in[4];
    const float* beta   = (const float*)d_in[5];
    const float* rmean  = (const float*)d_in[6];
    const float* rvar   = (const float*)d_in[7];
    float* out = (float*)d_out;

    cudaFuncSetAttribute(dcn_main, cudaFuncAttributeMaxDynamicSharedMemorySize,
                         SMEM_BYTES);

    pack_weights<<<2304, 256>>>(w_dcn, w_off);
    conv_off<<<B_ * H_, 256>>>(x, b_off);
    dcn_main<<<B_ * H_, 256, SMEM_BYTES>>>(x, gamma, beta, rmean, rvar, out);
}

// round 5
// speedup vs baseline: 2.8704x; 1.4154x over previous
#include <cuda_runtime.h>
#include <cuda_bf16.h>
#include <cstdint>
#include <math.h>

// Problem constants
#define B_  2
#define C1_ 256
#define C2_ 256
#define K2_ 9
#define H_  64
#define W_  64
#define HW_ 4096

// ---------------------------------------------------------------------------
// Scratch (allocation-free: __device__ globals)
// ---------------------------------------------------------------------------
__device__ float g_dy[B_ * K2_ * HW_];
__device__ float g_dx[B_ * K2_ * HW_];
__device__ float g_mask[B_ * K2_ * HW_];
__device__ float g_woffT[C1_ * 9 * 32];     // [(c*9+kk)][oc padded 32]
// Packed weights: [step(36)=tap*4+chunk][hl(2)][o(256)][72 bf16]
__device__ __align__(128) __nv_bfloat16 g_wA[36 * 2 * 256 * 72];

// ---------------------------------------------------------------------------
// PTX helpers (plain sm_103-legal: sm_80-era instructions)
// ---------------------------------------------------------------------------
__device__ __forceinline__ uint32_t smem_u32(const void* p) {
    uint32_t a;
    asm("{ .reg .u64 t; cvta.to.shared.u64 t, %1; cvt.u32.u64 %0, t; }"
        : "=r"(a) : "l"(p));
    return a;
}
__device__ __forceinline__ void cp_async16(uint32_t saddr, const void* gaddr) {
    asm volatile("cp.async.cg.shared.global [%0], [%1], 16;"
                 :: "r"(saddr), "l"(gaddr) : "memory");
}
__device__ __forceinline__ void cp_commit() {
    asm volatile("cp.async.commit_group;" ::: "memory");
}
__device__ __forceinline__ void cp_wait1() {
    asm volatile("cp.async.wait_group 1;" ::: "memory");
}
__device__ __forceinline__ void cp_wait0() {
    asm volatile("cp.async.wait_group 0;" ::: "memory");
}
__device__ __forceinline__ void bar_sync(int id, int cnt) {
    asm volatile("bar.sync %0, %1;" :: "r"(id), "r"(cnt) : "memory");
}
__device__ __forceinline__ void ldmatrix_x4(uint32_t& r0, uint32_t& r1,
                                            uint32_t& r2, uint32_t& r3,
                                            uint32_t addr) {
    asm volatile("ldmatrix.sync.aligned.m8n8.x4.shared.b16 {%0,%1,%2,%3}, [%4];"
                 : "=r"(r0), "=r"(r1), "=r"(r2), "=r"(r3) : "r"(addr));
}
__device__ __forceinline__ void mma_bf16(float& d0, float& d1, float& d2, float& d3,
                                         uint32_t a0, uint32_t a1, uint32_t a2, uint32_t a3,
                                         uint32_t b0, uint32_t b1) {
    asm volatile(
        "mma.sync.aligned.m16n8k16.row.col.f32.bf16.bf16.f32 "
        "{%0,%1,%2,%3}, {%4,%5,%6,%7}, {%8,%9}, {%0,%1,%2,%3};"
        : "+f"(d0), "+f"(d1), "+f"(d2), "+f"(d3)
        : "r"(a0), "r"(a1), "r"(a2), "r"(a3), "r"(b0), "r"(b1));
}

// ---------------------------------------------------------------------------
// Kernel 0: pack w_dcn -> bf16 hi/lo chunked blobs; transpose+pad w_off
// ---------------------------------------------------------------------------
__global__ void pack_weights(const float* __restrict__ w_dcn,
                             const float* __restrict__ w_off) {
    int idx = blockIdx.x * 256 + threadIdx.x;
    if (idx < 9 * 256 * 256) {
        int t = idx >> 16;
        int r = idx & 65535;
        int o = r >> 8;
        int c = r & 255;
        float w = w_dcn[o * (C1_ * K2_) + c * K2_ + t];
        __nv_bfloat16 hi = __float2bfloat16(w);
        __nv_bfloat16 lo = __float2bfloat16(w - __bfloat162float(hi));
        int chunk = c >> 6, cl = c & 63;
        size_t base = ((size_t)(t * 4 + chunk) * 2) * (256 * 72) + (size_t)o * 72 + cl;
        g_wA[base]            = hi;
        g_wA[base + 256 * 72] = lo;
    }
    if (idx < C1_ * 9 * 32) {
        int ck = idx >> 5, oc = idx & 31;
        g_woffT[idx] = (oc < 27) ? w_off[oc * (C1_ * 9) + ck] : 0.f;
    }
}

// ---------------------------------------------------------------------------
// Kernel 1: 3x3 offset conv -> dy, dx, sigmoid(mask)
// 256 threads = 4 oc-groups (8 each, padded) x 64 pixels. float4 weight LDS.
// ---------------------------------------------------------------------------
__global__ __launch_bounds__(256) void conv_off(const float* __restrict__ x,
                                                const float* __restrict__ b_off) {
    int b = blockIdx.x >> 6;
    int h = blockIdx.x & 63;
    int tid = threadIdx.x;
    int w = tid & 63;
    int g = tid >> 6;          // 0..3
    int oc0 = g * 8;

    __shared__ float xs[16][3][64];
    __shared__ __align__(16) float ws[16][9][32];

    float acc[8];
#pragma unroll
    for (int j = 0; j < 8; j++) acc[j] = 0.f;

    for (int cc = 0; cc < C1_; cc += 16) {
        for (int i = tid; i < 16 * 3 * 64; i += 256) {
            int c = i / 192, r = i % 192;
            int ky = r / 64, ww = r % 64;
            int y = h - 1 + ky;
            xs[c][ky][ww] = (y >= 0 && y < H_)
                ? x[((b * C1_ + cc + c) * H_ + y) * W_ + ww] : 0.f;
        }
        for (int i = tid; i < 16 * 9 * 32; i += 256) {
            ((float*)ws)[i] = g_woffT[(size_t)cc * 9 * 32 + i];
        }
        __syncthreads();

        for (int c = 0; c < 16; c++) {
#pragma unroll
            for (int kk = 0; kk < 9; kk++) {
                int ky = kk / 3, kx = kk % 3;
                int ww = w + kx - 1;
                float xv = (ww >= 0 && ww < W_) ? xs[c][ky][ww] : 0.f;
                const float4* wr = (const float4*)&ws[c][kk][oc0];
                float4 w0 = wr[0], w1 = wr[1];
                acc[0] += xv * w0.x; acc[1] += xv * w0.y;
                acc[2] += xv * w0.z; acc[3] += xv * w0.w;
                acc[4] += xv * w1.x; acc[5] += xv * w1.y;
                acc[6] += xv * w1.z; acc[7] += xv * w1.w;
            }
        }
        __syncthreads();
    }

#pragma unroll
    for (int j = 0; j < 8; j++) {
        int oc = oc0 + j;
        if (oc >= 27) break;
        float v = acc[j] + b_off[oc];
        if (oc < 18) {
            int k = oc >> 1;
            int oo = (b * K2_ + k) * HW_ + (h << 6) + w;
            if (oc & 1) g_dx[oo] = v; else g_dy[oo] = v;
        } else {
            int k = oc - 18;
            int oo = (b * K2_ + k) * HW_ + (h << 6) + w;
            g_mask[oo] = 1.f / (1.f + __expf(-v));
        }
    }
}

// ---------------------------------------------------------------------------
// Kernel 2: warp-specialized DCN. One CTA per (b,h).
// Warps 0-3: MMA consumers, warp w owns o in [64w, 64w+64).
// Warps 4-7: producers (metadata + gather + hi/lo split into B chunks).
// Pipeline over 36 steps (tap*4+chunk of 64 c), double-buffered B + per-warp
// double-buffered weights via cp.async.
// ---------------------------------------------------------------------------
#define WROW    72
#define WROWB   144
#define WBUF_B  18432u
#define WWARP_B 36864u
#define BBASE   147456u
#define BBUF_B  18432u
#define BHL_B   9216u
#define META_O  184320u
#define SMEM_BYTES 186368u

__global__ __launch_bounds__(256, 1) void dcn_main(const float* __restrict__ x,
                                                   const float* __restrict__ gamma,
                                                   const float* __restrict__ beta,
                                                   const float* __restrict__ rmean,
                                                   const float* __restrict__ rvar,
                                                   float* __restrict__ out) {
    extern __shared__ __align__(128) unsigned char smem_raw[];
    const uint32_t smem_base = smem_u32(smem_raw);

    int b = blockIdx.x >> 6;
    int h = blockIdx.x & 63;
    int tid = threadIdx.x;
    int wid = tid >> 5;
    int lane = tid & 31;

    float* swt  = (float*)(smem_raw + META_O);
    int*   sidx = (int*)(smem_raw + META_O + 1024);
    const float* xb = x + b * C1_ * HW_;

    if (wid >= 4) {
        // ================= PRODUCERS =================
        int ptid = tid - 128;
        int p  = ptid & 63;
        int cg = ptid >> 6;      // 0..1 -> 32 channels each

        auto make_meta = [&](int t) {
            if (ptid < 64) {
                int w = ptid;
                int oo = (b * K2_ + t) * HW_ + (h << 6) + w;
                float py = (float)(h - 1 + t / 3) + g_dy[oo];
                float px = (float)(w - 1 + t % 3) + g_dx[oo];
                float m = g_mask[oo];
                float y0f = floorf(py), x0f = floorf(px);
                float ly = py - y0f, lx = px - x0f;
                int y0 = (int)y0f, x0 = (int)x0f;
                int y1 = y0 + 1, x1 = x0 + 1;
                float vy0 = (y0 >= 0 && y0 < H_) ? 1.f : 0.f;
                float vy1 = (y1 >= 0 && y1 < H_) ? 1.f : 0.f;
                float vx0 = (x0 >= 0 && x0 < W_) ? 1.f : 0.f;
                float vx1 = (x1 >= 0 && x1 < W_) ? 1.f : 0.f;
                int cy0 = min(max(y0, 0), H_ - 1), cy1 = min(max(y1, 0), H_ - 1);
                int cx0 = min(max(x0, 0), W_ - 1), cx1 = min(max(x1, 0), W_ - 1);
                swt[0 * 64 + w] = (1.f - ly) * (1.f - lx) * m * vy0 * vx0;
                swt[1 * 64 + w] = (1.f - ly) * lx * m * vy0 * vx1;
                swt[2 * 64 + w] = ly * (1.f - lx) * m * vy1 * vx0;
                swt[3 * 64 + w] = ly * lx * m * vy1 * vx1;
                sidx[0 * 64 + w] = cy0 * W_ + cx0;
                sidx[1 * 64 + w] = cy0 * W_ + cx1;
                sidx[2 * 64 + w] = cy1 * W_ + cx0;
                sidx[3 * 64 + w] = cy1 * W_ + cx1;
            }
            bar_sync(2, 128);
        };

        auto make_chunk = [&](int s) {
            int q = s & 3;
            int i0 = sidx[p],       i1 = sidx[64 + p];
            int i2 = sidx[128 + p], i3 = sidx[192 + p];
            float w0 = swt[p],       w1 = swt[64 + p];
            float w2 = swt[128 + p], w3 = swt[192 + p];
            unsigned char* Bb = smem_raw + BBASE + (uint32_t)(s & 1) * BBUF_B;
            uint32_t rowoff = (uint32_t)p * WROWB;
#pragma unroll 4
            for (int it = 0; it < 16; ++it) {
                int cl = cg * 32 + it * 2;           // 0..62 within chunk
                int c0 = q * 64 + cl;
                const float* xa = xb + ((size_t)c0 << 12);
                const float* xc = xa + HW_;
                float va = xa[i0] * w0 + xa[i1] * w1 + xa[i2] * w2 + xa[i3] * w3;
                float vb = xc[i0] * w0 + xc[i1] * w1 + xc[i2] * w2 + xc[i3] * w3;
                __nv_bfloat162 hp = __floats2bfloat162_rn(va, vb);
                float ra = va - __bfloat162float(hp.x);
                float rb = vb - __bfloat162float(hp.y);
                __nv_bfloat162 lp = __floats2bfloat162_rn(ra, rb);
                uint32_t a = rowoff + (uint32_t)cl * 2;
                *(__nv_bfloat162*)(Bb + a)         = hp;
                *(__nv_bfloat162*)(Bb + BHL_B + a) = lp;
            }
        };

        make_meta(0);
        make_chunk(0);           // B(0) -> buf 0
        bar_sync(1, 256);
        for (int s = 0; s < 36; ++s) {
            if (s < 35) {
                int ns = s + 1;
                if ((ns & 3) == 0) make_meta(ns >> 2);
                make_chunk(ns);
            }
            bar_sync(1, 256);
        }
    } else {
        // ================= CONSUMERS =================
        int o0 = wid * 64;
        int a_row = lane & 15;
        int a_cad = (lane >= 16) ? 8 : 0;
        int b_row = (lane & 7) + ((lane >= 16) ? 8 : 0);
        int b_cad = ((lane >> 3) & 1) * 8;

        float acc[4][8][4];
#pragma unroll
        for (int mt = 0; mt < 4; mt++)
#pragma unroll
            for (int nt = 0; nt < 8; nt++)
#pragma unroll
                for (int j = 0; j < 4; j++) acc[mt][nt][j] = 0.f;

        const unsigned char* wsrc0 = (const unsigned char*)g_wA +
                                     (size_t)wid * 9216u;
        uint32_t wdst0 = smem_base + (uint32_t)wid * WWARP_B;

        // copy this warp's 64 o-rows (hi+lo) for step s: 2 x 9216 bytes
        auto cpW = [&](int s) {
            const unsigned char* src = wsrc0 + (size_t)s * 73728u;
            uint32_t dst = wdst0 + (uint32_t)(s & 1) * WBUF_B;
#pragma unroll
            for (int hl = 0; hl < 2; ++hl) {
#pragma unroll
                for (int j = 0; j < 18; ++j) {          // 18*32*16B = 9216B
                    uint32_t off = (uint32_t)(lane + j * 32) * 16u;
                    cp_async16(dst + (uint32_t)hl * BHL_B + off,
                               src + (size_t)hl * 36864u + off);
                }
            }
            cp_commit();
        };

        cpW(0);
        bar_sync(1, 256);

        for (int s = 0; s < 36; ++s) {
            if (s < 35) { cpW(s + 1); cp_wait1(); }
            else        { cp_wait0(); }

            uint32_t wreg = wdst0 + (uint32_t)(s & 1) * WBUF_B;
            uint32_t breg = smem_base + BBASE + (uint32_t)(s & 1) * BBUF_B;

#pragma unroll
            for (int ks = 0; ks < 4; ++ks) {
                uint32_t Bhf[16], Blf[16];
#pragma unroll
                for (int pr = 0; pr < 4; ++pr) {
                    uint32_t addr = breg +
                        (uint32_t)((pr * 16 + b_row) * WROW + ks * 16 + b_cad) * 2;
                    ldmatrix_x4(Bhf[pr * 4 + 0], Bhf[pr * 4 + 1],
                                Bhf[pr * 4 + 2], Bhf[pr * 4 + 3], addr);
                    ldmatrix_x4(Blf[pr * 4 + 0], Blf[pr * 4 + 1],
                                Blf[pr * 4 + 2], Blf[pr * 4 + 3], addr + BHL_B);
                }
#pragma unroll
                for (int mt = 0; mt < 4; ++mt) {
                    uint32_t aaddr = wreg +
                        (uint32_t)((mt * 16 + a_row) * WROW + ks * 16 + a_cad) * 2;
                    uint32_t Ah0, Ah1, Ah2, Ah3, Al0, Al1, Al2, Al3;
                    ldmatrix_x4(Ah0, Ah1, Ah2, Ah3, aaddr);
                    ldmatrix_x4(Al0, Al1, Al2, Al3, aaddr + BHL_B);
#pragma unroll
                    for (int nt = 0; nt < 8; ++nt) {
                        uint32_t bh0 = Bhf[nt * 2], bh1 = Bhf[nt * 2 + 1];
                        uint32_t bl0 = Blf[nt * 2], bl1 = Blf[nt * 2 + 1];
                        float* d = acc[mt][nt];
                        mma_bf16(d[0], d[1], d[2], d[3], Ah0, Ah1, Ah2, Ah3, bh0, bh1);
                        mma_bf16(d[0], d[1], d[2], d[3], Ah0, Ah1, Ah2, Ah3, bl0, bl1);
                        mma_bf16(d[0], d[1], d[2], d[3], Al0, Al1, Al2, Al3, bh0, bh1);
                    }
                }
            }
            bar_sync(1, 256);
        }

        // --- epilogue: BN + SiLU from register fragments
        int g4 = lane >> 2;
        int t4 = lane & 3;
#pragma unroll
        for (int mt = 0; mt < 4; ++mt) {
            int o_lo = o0 + mt * 16 + g4;
            int o_hi = o_lo + 8;
            float invl = gamma[o_lo] * rsqrtf(rvar[o_lo] + 1e-5f);
            float bbl  = beta[o_lo] - rmean[o_lo] * invl;
            float invh = gamma[o_hi] * rsqrtf(rvar[o_hi] + 1e-5f);
            float bbh  = beta[o_hi] - rmean[o_hi] * invh;
            float* opl = out + (((size_t)b * C2_ + o_lo) * H_ + h) * W_;
            float* oph = out + (((size_t)b * C2_ + o_hi) * H_ + h) * W_;
#pragma unroll
            for (int nt = 0; nt < 8; ++nt) {
                int pp = nt * 8 + t4 * 2;
                float y0v = acc[mt][nt][0] * invl + bbl;
                float y1v = acc[mt][nt][1] * invl + bbl;
                float y2v = acc[mt][nt][2] * invh + bbh;
                float y3v = acc[mt][nt][3] * invh + bbh;
                float2 vlo, vhi;
                vlo.x = y0v / (1.f + __expf(-y0v));
                vlo.y = y1v / (1.f + __expf(-y1v));
                vhi.x = y2v / (1.f + __expf(-y2v));
                vhi.y = y3v / (1.f + __expf(-y3v));
                *(float2*)(opl + pp) = vlo;
                *(float2*)(oph + pp) = vhi;
            }
        }
    }
}

// ---------------------------------------------------------------------------
extern "C" void kernel_launch(void* const* d_in, const int* in_sizes, int n_in,
                              void* d_out, int out_size) {
    const float* x      = (const float*)d_in[0];
    const float* w_off  = (const float*)d_in[1];
    const float* b_off  = (const float*)d_in[2];
    const float* w_dcn  = (const float*)d_in[3];
    const float* gamma  = (const float*)d_in[4];
    const float* beta   = (const float*)d_in[5];
    const float* rmean  = (const float*)d_in[6];
    const float* rvar   = (const float*)d_in[7];
    float* out = (float*)d_out;

    cudaFuncSetAttribute(dcn_main, cudaFuncAttributeMaxDynamicSharedMemorySize,
                         SMEM_BYTES);

    pack_weights<<<2304, 256>>>(w_dcn, w_off);
    conv_off<<<B_ * H_, 256>>>(x, b_off);
    dcn_main<<<B_ * H_, 256, SMEM_BYTES>>>(x, gamma, beta, rmean, rvar, out);
}

// round 6
// speedup vs baseline: 3.5483x; 1.2362x over previous
#include <cuda_runtime.h>
#include <cuda_bf16.h>
#include <cstdint>
#include <math.h>

// Problem constants
#define B_  2
#define C1_ 256
#define C2_ 256
#define K2_ 9
#define H_  64
#define W_  64
#define HW_ 4096

// ---------------------------------------------------------------------------
// Scratch (allocation-free: __device__ globals; zero-initialized pads)
// ---------------------------------------------------------------------------
// Main weights: [step(36)=tap*4+chunk][hl(2)][o(256)][72 bf16]
__device__ __align__(128) __nv_bfloat16 g_wA[36 * 2 * 256 * 72];
// Conv weights: [step(36)=kk*4+chunk][hl(2)][ocpad(32)][72 bf16]
__device__ __align__(128) __nv_bfloat16 g_wC[36 * 2 * 32 * 72];

// ---------------------------------------------------------------------------
// PTX helpers (plain sm_103-legal)
// ---------------------------------------------------------------------------
__device__ __forceinline__ uint32_t smem_u32(const void* p) {
    uint32_t a;
    asm("{ .reg .u64 t; cvta.to.shared.u64 t, %1; cvt.u32.u64 %0, t; }"
        : "=r"(a) : "l"(p));
    return a;
}
__device__ __forceinline__ void cp_async16(uint32_t saddr, const void* gaddr) {
    asm volatile("cp.async.cg.shared.global [%0], [%1], 16;"
                 :: "r"(saddr), "l"(gaddr) : "memory");
}
__device__ __forceinline__ void cp_commit() {
    asm volatile("cp.async.commit_group;" ::: "memory");
}
__device__ __forceinline__ void cp_wait1() {
    asm volatile("cp.async.wait_group 1;" ::: "memory");
}
__device__ __forceinline__ void cp_wait0() {
    asm volatile("cp.async.wait_group 0;" ::: "memory");
}
__device__ __forceinline__ void bar_sync(int id, int cnt) {
    asm volatile("bar.sync %0, %1;" :: "r"(id), "r"(cnt) : "memory");
}
__device__ __forceinline__ void ldmatrix_x4(uint32_t& r0, uint32_t& r1,
                                            uint32_t& r2, uint32_t& r3,
                                            uint32_t addr) {
    asm volatile("ldmatrix.sync.aligned.m8n8.x4.shared.b16 {%0,%1,%2,%3}, [%4];"
                 : "=r"(r0), "=r"(r1), "=r"(r2), "=r"(r3) : "r"(addr));
}
__device__ __forceinline__ void mma_bf16(float& d0, float& d1, float& d2, float& d3,
                                         uint32_t a0, uint32_t a1, uint32_t a2, uint32_t a3,
                                         uint32_t b0, uint32_t b1) {
    asm volatile(
        "mma.sync.aligned.m16n8k16.row.col.f32.bf16.bf16.f32 "
        "{%0,%1,%2,%3}, {%4,%5,%6,%7}, {%8,%9}, {%0,%1,%2,%3};"
        : "+f"(d0), "+f"(d1), "+f"(d2), "+f"(d3)
        : "r"(a0), "r"(a1), "r"(a2), "r"(a3), "r"(b0), "r"(b1));
}

// ---------------------------------------------------------------------------
// Kernel 0: pack w_dcn + w_off into bf16 hi/lo blobs
// ---------------------------------------------------------------------------
__global__ void pack_weights(const float* __restrict__ w_dcn,
                             const float* __restrict__ w_off) {
    int idx = blockIdx.x * 256 + threadIdx.x;
    if (idx < 9 * 256 * 256) {
        int t = idx >> 16;
        int r = idx & 65535;
        int o = r >> 8;
        int c = r & 255;
        float w = w_dcn[o * (C1_ * K2_) + c * K2_ + t];
        __nv_bfloat16 hi = __float2bfloat16(w);
        __nv_bfloat16 lo = __float2bfloat16(w - __bfloat162float(hi));
        int chunk = c >> 6, cl = c & 63;
        size_t base = ((size_t)(t * 4 + chunk) * 2) * (256 * 72) + (size_t)o * 72 + cl;
        g_wA[base]            = hi;
        g_wA[base + 256 * 72] = lo;
    }
    // conv weights: K order = kk*256 + c ; step = kk*4 + (c>>6)
    if (idx < 27 * 2304) {
        int oc = idx / 2304;
        int r  = idx % 2304;
        int c  = r >> 3 /*unused*/, kk;
        // decode r = c*9 + kk from w_off layout [oc][c][3][3]
        c  = r / 9;
        kk = r % 9;
        float w = w_off[idx];
        __nv_bfloat16 hi = __float2bfloat16(w);
        __nv_bfloat16 lo = __float2bfloat16(w - __bfloat162float(hi));
        int s = kk * 4 + (c >> 6);
        int cl = c & 63;
        size_t base = (size_t)s * (2 * 32 * 72) + (size_t)oc * 72 + cl;
        g_wC[base]           = hi;
        g_wC[base + 32 * 72] = lo;
    }
}

// ---------------------------------------------------------------------------
// Fused kernel: conv-offset GEMM (phase 1) + DCN GEMM (phase 2) + BN + SiLU
// One CTA per (b,h). Warps 0-3 consumers (MMA), warps 4-7 producers.
// ---------------------------------------------------------------------------
#define WROW    72
#define WROWB   144
#define WBUF_B  18432u
#define WWARP_B 36864u
#define BBASE   147456u
#define BBUF_B  18432u
#define BHL_B   9216u
#define META_O  184320u
// META: swt[256]f (1024) | sidx[256]i (1024) | om[32*64]f (8192)
#define SMEM_BYTES (META_O + 2048u + 8192u)

__global__ __launch_bounds__(256, 1) void dcn_fused(const float* __restrict__ x,
                                                    const float* __restrict__ b_off,
                                                    const float* __restrict__ gamma,
                                                    const float* __restrict__ beta,
                                                    const float* __restrict__ rmean,
                                                    const float* __restrict__ rvar,
                                                    float* __restrict__ out) {
    extern __shared__ __align__(128) unsigned char smem_raw[];
    const uint32_t smem_base = smem_u32(smem_raw);

    int b = blockIdx.x >> 6;
    int h = blockIdx.x & 63;
    int tid = threadIdx.x;
    int wid = tid >> 5;
    int lane = tid & 31;

    float* swt  = (float*)(smem_raw + META_O);
    int*   sidx = (int*)(smem_raw + META_O + 1024);
    float* om   = (float*)(smem_raw + META_O + 2048);   // [oc][64]
    const float* xb = x + b * C1_ * HW_;

    if (wid >= 4) {
        // ========================= PRODUCERS =========================
        int ptid = tid - 128;
        int p  = ptid & 63;
        int cg = ptid >> 6;      // 0..1 -> 32 channels each

        // ---- phase 1: im2col chunk for conv (step s: kk = s>>2, c0 = (s&3)*64)
        auto conv_chunk = [&](int s) {
            int kk = s >> 2, q = s & 3;
            int ky = kk / 3, kx = kk % 3;
            int y = h - 1 + ky;
            int col = p - 1 + kx;
            bool valid = (y >= 0) && (y < H_) && (col >= 0) && (col < W_);
            unsigned char* Bb = smem_raw + BBASE + (uint32_t)(s & 1) * BBUF_B;
            uint32_t rowoff = (uint32_t)p * WROWB;
#pragma unroll 4
            for (int it = 0; it < 16; ++it) {
                int cl = cg * 32 + it * 2;
                int c0 = q * 64 + cl;
                float va = 0.f, vb = 0.f;
                if (valid) {
                    const float* xa = xb + ((size_t)c0 << 12) + y * W_ + col;
                    va = xa[0];
                    vb = xa[HW_];
                }
                __nv_bfloat162 hp = __floats2bfloat162_rn(va, vb);
                float ra = va - __bfloat162float(hp.x);
                float rb = vb - __bfloat162float(hp.y);
                __nv_bfloat162 lp = __floats2bfloat162_rn(ra, rb);
                uint32_t a = rowoff + (uint32_t)cl * 2;
                *(__nv_bfloat162*)(Bb + a)         = hp;
                *(__nv_bfloat162*)(Bb + BHL_B + a) = lp;
            }
        };

        conv_chunk(0);
        bar_sync(1, 256);
        for (int s = 0; s < 36; ++s) {
            if (s < 35) conv_chunk(s + 1);
            bar_sync(1, 256);
        }
        bar_sync(1, 256);        // consumers write om

        // ---- phase 2: bilinear metadata + gather
        auto make_meta = [&](int t) {
            if (ptid < 64) {
                int w = ptid;
                float py = (float)(h - 1 + t / 3) + om[(2 * t) * 64 + w];
                float px = (float)(w - 1 + t % 3) + om[(2 * t + 1) * 64 + w];
                float m = 1.f / (1.f + __expf(-om[(18 + t) * 64 + w]));
                float y0f = floorf(py), x0f = floorf(px);
                float ly = py - y0f, lx = px - x0f;
                int y0 = (int)y0f, x0 = (int)x0f;
                int y1 = y0 + 1, x1 = x0 + 1;
                float vy0 = (y0 >= 0 && y0 < H_) ? 1.f : 0.f;
                float vy1 = (y1 >= 0 && y1 < H_) ? 1.f : 0.f;
                float vx0 = (x0 >= 0 && x0 < W_) ? 1.f : 0.f;
                float vx1 = (x1 >= 0 && x1 < W_) ? 1.f : 0.f;
                int cy0 = min(max(y0, 0), H_ - 1), cy1 = min(max(y1, 0), H_ - 1);
                int cx0 = min(max(x0, 0), W_ - 1), cx1 = min(max(x1, 0), W_ - 1);
                swt[0 * 64 + w] = (1.f - ly) * (1.f - lx) * m * vy0 * vx0;
                swt[1 * 64 + w] = (1.f - ly) * lx * m * vy0 * vx1;
                swt[2 * 64 + w] = ly * (1.f - lx) * m * vy1 * vx0;
                swt[3 * 64 + w] = ly * lx * m * vy1 * vx1;
                sidx[0 * 64 + w] = cy0 * W_ + cx0;
                sidx[1 * 64 + w] = cy0 * W_ + cx1;
                sidx[2 * 64 + w] = cy1 * W_ + cx0;
                sidx[3 * 64 + w] = cy1 * W_ + cx1;
            }
            bar_sync(2, 128);
        };

        auto make_chunk = [&](int s) {
            int q = s & 3;
            int i0 = sidx[p],       i1 = sidx[64 + p];
            int i2 = sidx[128 + p], i3 = sidx[192 + p];
            float w0 = swt[p],       w1 = swt[64 + p];
            float w2 = swt[128 + p], w3 = swt[192 + p];
            unsigned char* Bb = smem_raw + BBASE + (uint32_t)(s & 1) * BBUF_B;
            uint32_t rowoff = (uint32_t)p * WROWB;
#pragma unroll 4
            for (int it = 0; it < 16; ++it) {
                int cl = cg * 32 + it * 2;
                int c0 = q * 64 + cl;
                const float* xa = xb + ((size_t)c0 << 12);
                const float* xc = xa + HW_;
                float va = xa[i0] * w0 + xa[i1] * w1 + xa[i2] * w2 + xa[i3] * w3;
                float vb = xc[i0] * w0 + xc[i1] * w1 + xc[i2] * w2 + xc[i3] * w3;
                __nv_bfloat162 hp = __floats2bfloat162_rn(va, vb);
                float ra = va - __bfloat162float(hp.x);
                float rb = vb - __bfloat162float(hp.y);
                __nv_bfloat162 lp = __floats2bfloat162_rn(ra, rb);
                uint32_t a = rowoff + (uint32_t)cl * 2;
                *(__nv_bfloat162*)(Bb + a)         = hp;
                *(__nv_bfloat162*)(Bb + BHL_B + a) = lp;
            }
        };

        make_meta(0);
        make_chunk(0);
        bar_sync(1, 256);
        for (int s = 0; s < 36; ++s) {
            if (s < 35) {
                int ns = s + 1;
                if ((ns & 3) == 0) make_meta(ns >> 2);
                make_chunk(ns);
            }
            bar_sync(1, 256);
        }
    } else {
        // ========================= CONSUMERS =========================
        int a_row = lane & 15;
        int a_cad = (lane >= 16) ? 8 : 0;
        int b_row = (lane & 7) + ((lane >= 16) ? 8 : 0);
        int b_cad = ((lane >> 3) & 1) * 8;
        int g4 = lane >> 2;
        int t4 = lane & 3;

        uint32_t wdst0 = smem_base + (uint32_t)wid * WWARP_B;

        // ---- phase 1: conv MMA (m=32 oc, warp owns 16 px = n [16w,16w+16))
        {
            float accC[2][2][4];
#pragma unroll
            for (int mt = 0; mt < 2; mt++)
#pragma unroll
                for (int nt = 0; nt < 2; nt++)
#pragma unroll
                    for (int j = 0; j < 4; j++) accC[mt][nt][j] = 0.f;

            auto cpWC = [&](int s) {
                const unsigned char* src =
                    (const unsigned char*)g_wC + (size_t)s * 9216u;
                uint32_t dst = wdst0 + (uint32_t)(s & 1) * WBUF_B;
#pragma unroll
                for (int hl = 0; hl < 2; ++hl) {
#pragma unroll
                    for (int j = 0; j < 9; ++j) {       // 9*32*16B = 4608B
                        uint32_t off = (uint32_t)(lane + j * 32) * 16u;
                        cp_async16(dst + (uint32_t)hl * BHL_B + off,
                                   src + (size_t)hl * 4608u + off);
                    }
                }
                cp_commit();
            };

            cpWC(0);
            bar_sync(1, 256);

            for (int s = 0; s < 36; ++s) {
                if (s < 35) { cpWC(s + 1); cp_wait1(); }
                else        { cp_wait0(); }

                uint32_t wreg = wdst0 + (uint32_t)(s & 1) * WBUF_B;
                uint32_t breg = smem_base + BBASE + (uint32_t)(s & 1) * BBUF_B;

#pragma unroll
                for (int ks = 0; ks < 4; ++ks) {
                    uint32_t addrB = breg +
                        (uint32_t)((wid * 16 + b_row) * WROW + ks * 16 + b_cad) * 2;
                    uint32_t Bh0, Bh1, Bh2, Bh3, Bl0, Bl1, Bl2, Bl3;
                    ldmatrix_x4(Bh0, Bh1, Bh2, Bh3, addrB);
                    ldmatrix_x4(Bl0, Bl1, Bl2, Bl3, addrB + BHL_B);
#pragma unroll
                    for (int mt = 0; mt < 2; ++mt) {
                        uint32_t aaddr = wreg +
                            (uint32_t)((mt * 16 + a_row) * WROW + ks * 16 + a_cad) * 2;
                        uint32_t Ah0, Ah1, Ah2, Ah3, Al0, Al1, Al2, Al3;
                        ldmatrix_x4(Ah0, Ah1, Ah2, Ah3, aaddr);
                        ldmatrix_x4(Al0, Al1, Al2, Al3, aaddr + BHL_B);
                        float* d0 = accC[mt][0];
                        float* d1 = accC[mt][1];
                        mma_bf16(d0[0], d0[1], d0[2], d0[3], Ah0, Ah1, Ah2, Ah3, Bh0, Bh1);
                        mma_bf16(d0[0], d0[1], d0[2], d0[3], Ah0, Ah1, Ah2, Ah3, Bl0, Bl1);
                        mma_bf16(d0[0], d0[1], d0[2], d0[3], Al0, Al1, Al2, Al3, Bh0, Bh1);
                        mma_bf16(d1[0], d1[1], d1[2], d1[3], Ah0, Ah1, Ah2, Ah3, Bh2, Bh3);
                        mma_bf16(d1[0], d1[1], d1[2], d1[3], Ah0, Ah1, Ah2, Ah3, Bl2, Bl3);
                        mma_bf16(d1[0], d1[1], d1[2], d1[3], Al0, Al1, Al2, Al3, Bh2, Bh3);
                    }
                }
                bar_sync(1, 256);
            }

            // conv epilogue -> om smem (+ bias)
#pragma unroll
            for (int mt = 0; mt < 2; ++mt) {
                int oc_lo = mt * 16 + g4;
                int oc_hi = oc_lo + 8;
#pragma unroll
                for (int nt = 0; nt < 2; ++nt) {
                    int col = wid * 16 + nt * 8 + t4 * 2;
                    if (oc_lo < 27) {
                        float bo = b_off[oc_lo];
                        om[oc_lo * 64 + col]     = accC[mt][nt][0] + bo;
                        om[oc_lo * 64 + col + 1] = accC[mt][nt][1] + bo;
                    }
                    if (oc_hi < 27) {
                        float bo = b_off[oc_hi];
                        om[oc_hi * 64 + col]     = accC[mt][nt][2] + bo;
                        om[oc_hi * 64 + col + 1] = accC[mt][nt][3] + bo;
                    }
                }
            }
            bar_sync(1, 256);    // om ready for producers
        }

        // ---- phase 2: main DCN MMA (warp owns o in [64w, 64w+64))
        int o0 = wid * 64;
        float acc[4][8][4];
#pragma unroll
        for (int mt = 0; mt < 4; mt++)
#pragma unroll
            for (int nt = 0; nt < 8; nt++)
#pragma unroll
                for (int j = 0; j < 4; j++) acc[mt][nt][j] = 0.f;

        const unsigned char* wsrc0 = (const unsigned char*)g_wA +
                                     (size_t)wid * 9216u;

        auto cpW = [&](int s) {
            const unsigned char* src = wsrc0 + (size_t)s * 73728u;
            uint32_t dst = wdst0 + (uint32_t)(s & 1) * WBUF_B;
#pragma unroll
            for (int hl = 0; hl < 2; ++hl) {
#pragma unroll
                for (int j = 0; j < 18; ++j) {          // 18*32*16B = 9216B
                    uint32_t off = (uint32_t)(lane + j * 32) * 16u;
                    cp_async16(dst + (uint32_t)hl * BHL_B + off,
                               src + (size_t)hl * 36864u + off);
                }
            }
            cp_commit();
        };

        cpW(0);
        bar_sync(1, 256);

        for (int s = 0; s < 36; ++s) {
            if (s < 35) { cpW(s + 1); cp_wait1(); }
            else        { cp_wait0(); }

            uint32_t wreg = wdst0 + (uint32_t)(s & 1) * WBUF_B;
            uint32_t breg = smem_base + BBASE + (uint32_t)(s & 1) * BBUF_B;

#pragma unroll
            for (int ks = 0; ks < 4; ++ks) {
                uint32_t Bhf[16], Blf[16];
#pragma unroll
                for (int pr = 0; pr < 4; ++pr) {
                    uint32_t addr = breg +
                        (uint32_t)((pr * 16 + b_row) * WROW + ks * 16 + b_cad) * 2;
                    ldmatrix_x4(Bhf[pr * 4 + 0], Bhf[pr * 4 + 1],
                                Bhf[pr * 4 + 2], Bhf[pr * 4 + 3], addr);
                    ldmatrix_x4(Blf[pr * 4 + 0], Blf[pr * 4 + 1],
                                Blf[pr * 4 + 2], Blf[pr * 4 + 3], addr + BHL_B);
                }
#pragma unroll
                for (int mt = 0; mt < 4; ++mt) {
                    uint32_t aaddr = wreg +
                        (uint32_t)((mt * 16 + a_row) * WROW + ks * 16 + a_cad) * 2;
                    uint32_t Ah0, Ah1, Ah2, Ah3, Al0, Al1, Al2, Al3;
                    ldmatrix_x4(Ah0, Ah1, Ah2, Ah3, aaddr);
                    ldmatrix_x4(Al0, Al1, Al2, Al3, aaddr + BHL_B);
#pragma unroll
                    for (int nt = 0; nt < 8; ++nt) {
                        uint32_t bh0 = Bhf[nt * 2], bh1 = Bhf[nt * 2 + 1];
                        uint32_t bl0 = Blf[nt * 2], bl1 = Blf[nt * 2 + 1];
                        float* d = acc[mt][nt];
                        mma_bf16(d[0], d[1], d[2], d[3], Ah0, Ah1, Ah2, Ah3, bh0, bh1);
                        mma_bf16(d[0], d[1], d[2], d[3], Ah0, Ah1, Ah2, Ah3, bl0, bl1);
                        mma_bf16(d[0], d[1], d[2], d[3], Al0, Al1, Al2, Al3, bh0, bh1);
                    }
                }
            }
            bar_sync(1, 256);
        }

        // ---- epilogue: BN + SiLU
#pragma unroll
        for (int mt = 0; mt < 4; ++mt) {
            int o_lo = o0 + mt * 16 + g4;
            int o_hi = o_lo + 8;
            float invl = gamma[o_lo] * rsqrtf(rvar[o_lo] + 1e-5f);
            float bbl  = beta[o_lo] - rmean[o_lo] * invl;
            float invh = gamma[o_hi] * rsqrtf(rvar[o_hi] + 1e-5f);
            float bbh  = beta[o_hi] - rmean[o_hi] * invh;
            float* opl = out + (((size_t)b * C2_ + o_lo) * H_ + h) * W_;
            float* oph = out + (((size_t)b * C2_ + o_hi) * H_ + h) * W_;
#pragma unroll
            for (int nt = 0; nt < 8; ++nt) {
                int pp = nt * 8 + t4 * 2;
                float y0v = acc[mt][nt][0] * invl + bbl;
                float y1v = acc[mt][nt][1] * invl + bbl;
                float y2v = acc[mt][nt][2] * invh + bbh;
                float y3v = acc[mt][nt][3] * invh + bbh;
                float2 vlo, vhi;
                vlo.x = y0v / (1.f + __expf(-y0v));
                vlo.y = y1v / (1.f + __expf(-y1v));
                vhi.x = y2v / (1.f + __expf(-y2v));
                vhi.y = y3v / (1.f + __expf(-y3v));
                *(float2*)(opl + pp) = vlo;
                *(float2*)(oph + pp) = vhi;
            }
        }
    }
}

// ---------------------------------------------------------------------------
extern "C" void kernel_launch(void* const* d_in, const int* in_sizes, int n_in,
                              void* d_out, int out_size) {
    const float* x      = (const float*)d_in[0];
    const float* w_off  = (const float*)d_in[1];
    const float* b_off  = (const float*)d_in[2];
    const float* w_dcn  = (const float*)d_in[3];
    const float* gamma  = (const float*)d_in[4];
    const float* beta   = (const float*)d_in[5];
    const float* rmean  = (const float*)d_in[6];
    const float* rvar   = (const float*)d_in[7];
    float* out = (float*)d_out;

    cudaFuncSetAttribute(dcn_fused, cudaFuncAttributeMaxDynamicSharedMemorySize,
                         SMEM_BYTES);

    pack_weights<<<2304, 256>>>(w_dcn, w_off);
    dcn_fused<<<B_ * H_, 256, SMEM_BYTES>>>(x, b_off, gamma, beta, rmean, rvar, out);
}